// round 6
// baseline (speedup 1.0000x reference)
#include <cuda_runtime.h>
#include <cuda_bf16.h>

// Problem constants (fixed by dataset): B=16, C=80, D=1024, S=14 (P=196)
#define BB 16
#define CC 80
#define DD 1024
#define PP 196
#define PT 4            // pixels per block in phase 1 (2 warps per pixel, d-split)
#define SSTRIDE 1032    // padded smem stride for img staging
#define CHUNK 16        // word rows per smem chunk (64KB)

// Scratch (no allocation allowed -> device globals)
__device__ float g_imgT[BB * PP * DD];        // [b][p][d]  transposed img, 12.8MB
__device__ float g_part[BB * CC * 2 * PP];    // [b][c][half][p] partial scores
__device__ float g_coef[BB * PP * CC];        // [b][p][c]

typedef unsigned long long ull;

__device__ __forceinline__ float tanh_fast(float x) {
    float y; asm("tanh.approx.f32 %0, %1;" : "=f"(y) : "f"(x)); return y;
}
__device__ __forceinline__ ull pack2(float a, float b) {
    ull r; asm("mov.b64 %0, {%1, %2};" : "=l"(r) : "f"(a), "f"(b)); return r;
}
__device__ __forceinline__ ull fma2(ull a, ull b, ull c) {
    ull d; asm("fma.rn.f32x2 %0, %1, %2, %3;" : "=l"(d) : "l"(a), "l"(b), "l"(c)); return d;
}
__device__ __forceinline__ float2 unpack2(ull a) {
    float lo, hi; asm("mov.b64 {%0, %1}, %2;" : "=f"(lo), "=f"(hi) : "l"(a));
    return make_float2(lo, hi);
}

// ---------------------------------------------------------------------------
// Phase 1: part[b,c,h,p] = sum_{d in half h} tanh(img[b,d,p]*word[c,d])*w[d]
// Also writes imgT[b,p,d] (coalesced) for phase 3.
// grid (49, 16), block 256 (8 warps = 4 pixels x 2 d-halves), 3 blocks/SM.
// Each warp caches only 16 d-quads (im[4]+wv[4] = 32 regs), leaving ptxas
// ~30 registers for software-pipelining the LDS.128 + tanh chains.
// ---------------------------------------------------------------------------
__global__ __launch_bounds__(256, 3) void scores_kernel(
    const float* __restrict__ img,      // [B][D][P]
    const float* __restrict__ word,     // [C][D]
    const float* __restrict__ faw)      // [D]
{
    extern __shared__ float sm[];               // 64KB: img staging, then word chunks

    const int b  = blockIdx.y;
    const int p0 = blockIdx.x * PT;
    const int tid = threadIdx.x;

    // --- Stage img tile: [PT pixels][D] -> smem (49*4 = 196 exactly, no tail) ---
    const float* imgb = img + (size_t)b * DD * PP;
    for (int i = tid; i < PT * DD; i += 256) {
        int p = i & (PT - 1), d = i >> 2;
        sm[p * SSTRIDE + d] = imgb[d * PP + p0 + p];
    }
    __syncthreads();

    const int lane = tid & 31, w = tid >> 5;
    const int pw = w >> 1;              // pixel within block (0..3)
    const int h  = w & 1;               // d-half (0..1)
    const int p  = p0 + pw;
    const int q0 = h * 128;             // first d-quad owned by this warp

    // Register-cache this warp's img half-slice + fc_a_w half-slice,
    // and emit transposed img (coalesced float4 stores) for phase 3.
    float4 im[4], wv[4];
    const float4* faw4 = (const float4*)faw;
    {
        float4* outT = (float4*)(g_imgT + ((size_t)b * PP + p) * DD);
        #pragma unroll
        for (int k = 0; k < 4; k++) {
            int d4 = q0 + lane + 32 * k;
            float4 v = *(const float4*)&sm[pw * SSTRIDE + 4 * d4];
            im[k] = v;
            wv[k] = faw4[d4];
            outT[d4] = v;
        }
    }
    __syncthreads();   // img staging dead; smem now belongs to word chunks

    float* scb = g_part + (((size_t)b * CC) * 2 + h) * PP + p;
    const float4* word4 = (const float4*)word;

    #pragma unroll 1
    for (int c0 = 0; c0 < CC; c0 += CHUNK) {
        // Cooperative load of CHUNK word rows (64KB), coalesced LDG.128
        const float4* src = word4 + (size_t)c0 * (DD / 4);
        #pragma unroll
        for (int i = 0; i < CHUNK * DD / 4 / 256; i++)
            ((float4*)sm)[tid + 256 * i] = src[tid + 256 * i];
        __syncthreads();

        #pragma unroll 1
        for (int cc = 0; cc < CHUNK; cc++) {
            const float4* ws = (const float4*)sm + cc * (DD / 4) + q0;
            float a0 = 0.f, a1 = 0.f, a2 = 0.f, a3 = 0.f;
            #pragma unroll
            for (int k = 0; k < 4; k++) {
                float4 wd = ws[lane + 32 * k];       // conflict-free LDS.128
                a0 = fmaf(tanh_fast(im[k].x * wd.x), wv[k].x, a0);
                a1 = fmaf(tanh_fast(im[k].y * wd.y), wv[k].y, a1);
                a2 = fmaf(tanh_fast(im[k].z * wd.z), wv[k].z, a2);
                a3 = fmaf(tanh_fast(im[k].w * wd.w), wv[k].w, a3);
            }
            float acc = (a0 + a1) + (a2 + a3);
            #pragma unroll
            for (int o = 16; o; o >>= 1)
                acc += __shfl_xor_sync(0xFFFFFFFFu, acc, o);
            if (lane == 0)
                scb[(size_t)(c0 + cc) * 2 * PP] = acc;
            // fc_a_b is a uniform shift over spatial scores -> softmax-invariant
        }
        __syncthreads();   // chunk consumed; safe to overwrite
    }
}

// ---------------------------------------------------------------------------
// Phase 2: coef[b,p,c] = softmax over p of (part[b,c,0,p] + part[b,c,1,p]).
// One warp per (b,c). grid 160, block 256.
// ---------------------------------------------------------------------------
__global__ __launch_bounds__(256) void softmax_kernel()
{
    const int gw   = blockIdx.x * 8 + (threadIdx.x >> 5);   // 0..1279
    const int lane = threadIdx.x & 31;
    const int b = gw / CC, c = gw % CC;

    const float* sc = g_part + ((size_t)b * CC + c) * 2 * PP;
    float v[7];
    float mx = -1e30f;
    #pragma unroll
    for (int k = 0; k < 7; k++) {
        int p = lane + 32 * k;
        v[k] = (p < PP) ? (sc[p] + sc[PP + p]) : -1e30f;
        mx = fmaxf(mx, v[k]);
    }
    #pragma unroll
    for (int o = 16; o; o >>= 1)
        mx = fmaxf(mx, __shfl_xor_sync(0xFFFFFFFFu, mx, o));

    float sum = 0.f;
    #pragma unroll
    for (int k = 0; k < 7; k++) {
        v[k] = __expf(v[k] - mx);      // invalid p -> exp(-inf) = 0
        sum += v[k];
    }
    #pragma unroll
    for (int o = 16; o; o >>= 1)
        sum += __shfl_xor_sync(0xFFFFFFFFu, sum, o);

    float inv = 1.0f / sum;
    #pragma unroll
    for (int k = 0; k < 7; k++) {
        int p = lane + 32 * k;
        if (p < PP)
            g_coef[((size_t)b * PP + p) * CC + c] = v[k] * inv;
    }
}

// ---------------------------------------------------------------------------
// Phase 3: out[b,c,d] = sum_p coef[b,p,c] * imgT[b,p,d]
// grid (8 d-tiles of 128, 16 b), block 256 (163KB dyn smem, 1 block/SM).
// Thread tile: 10 c x 4 d, packed fma.rn.f32x2 (pairs over c).
// ---------------------------------------------------------------------------
__global__ __launch_bounds__(256) void out_kernel(float* __restrict__ out)
{
    extern __shared__ float sm[];
    float* img_s  = sm;                 // [196][128]
    float* coef_s = sm + PP * 128;      // [196][80]

    const int b  = blockIdx.y;
    const int d0 = blockIdx.x * 128;
    const int tid = threadIdx.x;

    const float* imgT = g_imgT + (size_t)b * PP * DD;
    for (int i = tid; i < PP * 32; i += 256) {   // 196 * 128/4 float4s
        int pp = i >> 5, j = i & 31;
        ((float4*)img_s)[pp * 32 + j] = *(const float4*)(imgT + (size_t)pp * DD + d0 + 4 * j);
    }
    const float4* coefb = (const float4*)(g_coef + (size_t)b * PP * CC);
    for (int i = tid; i < PP * 20; i += 256)     // 196 * 80/4 float4s
        ((float4*)coef_s)[i] = coefb[i];
    __syncthreads();

    const int dg = tid & 31;            // lanes over d-quads (conflict-free LDS.128)
    const int cg = tid >> 5;            // warp = c-group (broadcast coef LDS.64)

    ull acc[5][4];
    #pragma unroll
    for (int j = 0; j < 5; j++)
        #pragma unroll
        for (int dd = 0; dd < 4; dd++) acc[j][dd] = 0ull;

    #pragma unroll 2
    for (int p = 0; p < PP; p++) {
        float4 iv = ((const float4*)img_s)[p * 32 + dg];
        ull ix = pack2(iv.x, iv.x);
        ull iy = pack2(iv.y, iv.y);
        ull iz = pack2(iv.z, iv.z);
        ull iw = pack2(iv.w, iv.w);
        const ull* cpr = (const ull*)(coef_s + p * CC + cg * 10);
        #pragma unroll
        for (int j = 0; j < 5; j++) {
            ull cc = cpr[j];            // (coef[c], coef[c+1])
            acc[j][0] = fma2(cc, ix, acc[j][0]);
            acc[j][1] = fma2(cc, iy, acc[j][1]);
            acc[j][2] = fma2(cc, iz, acc[j][2]);
            acc[j][3] = fma2(cc, iw, acc[j][3]);
        }
    }

    #pragma unroll
    for (int j = 0; j < 5; j++) {
        int c = cg * 10 + 2 * j;
        #pragma unroll
        for (int dd = 0; dd < 4; dd++) {
            float2 v = unpack2(acc[j][dd]);
            int d = d0 + 4 * dg + dd;
            out[((size_t)(b * CC + c))     * DD + d] = v.x;
            out[((size_t)(b * CC + c + 1)) * DD + d] = v.y;
        }
    }
}

// ---------------------------------------------------------------------------
extern "C" void kernel_launch(void* const* d_in, const int* in_sizes, int n_in,
                              void* d_out, int out_size)
{
    // inputs: [0]=batch_size (unused), [1]=img [16,1024,14,14],
    //         [2]=word [80,1024], [3]=fc_a_w [1024], [4]=fc_a_b (softmax-invariant)
    const float* img  = (const float*)d_in[1];
    const float* word = (const float*)d_in[2];
    const float* faw  = (const float*)d_in[3];
    float* out = (float*)d_out;

    const int smem1 = CHUNK * DD * (int)sizeof(float);            // 65,536 B
    const int smem3 = (PP * 128 + PP * CC) * (int)sizeof(float);  // 163,072 B
    cudaFuncSetAttribute(scores_kernel, cudaFuncAttributeMaxDynamicSharedMemorySize, smem1);
    cudaFuncSetAttribute(out_kernel, cudaFuncAttributeMaxDynamicSharedMemorySize, smem3);

    scores_kernel<<<dim3(49, BB), 256, smem1>>>(img, word, faw);
    softmax_kernel<<<160, 256>>>();
    out_kernel<<<dim3(8, BB), 256, smem3>>>(out);
}

// round 7
// speedup vs baseline: 1.1129x; 1.1129x over previous
#include <cuda_runtime.h>
#include <cuda_bf16.h>
#include <cuda_fp16.h>

// Problem constants (fixed by dataset): B=16, C=80, D=1024, S=14 (P=196)
#define BB 16
#define CC 80
#define DD 1024
#define PP 196
#define PT 8            // pixels per block in phase 1
#define SSTRIDE 1032    // padded smem stride for img staging
#define CHUNK 16        // word rows per smem chunk (32KB as f16x2)

// Scratch (no allocation allowed -> device globals)
__device__ float g_imgT[BB * PP * DD];        // [b][p][d]  transposed img, 12.8MB
__device__ float g_scores[BB * CC * PP];      // [b][c][p]
__device__ float g_coef[BB * PP * CC];        // [b][p][c]

typedef unsigned u32;
typedef unsigned long long ull;

__device__ __forceinline__ u32 hmul2(u32 a, u32 b) {
    u32 r; asm("mul.rn.f16x2 %0, %1, %2;" : "=r"(r) : "r"(a), "r"(b)); return r;
}
__device__ __forceinline__ u32 htanh2(u32 a) {
    u32 r; asm("tanh.approx.f16x2 %0, %1;" : "=r"(r) : "r"(a)); return r;
}
// d = {hi -> upper 16, lo -> lower 16}
__device__ __forceinline__ u32 pack_f16x2(float hi, float lo) {
    u32 r; asm("cvt.rn.f16x2.f32 %0, %1, %2;" : "=r"(r) : "f"(hi), "f"(lo)); return r;
}
__device__ __forceinline__ float2 unpack_f16x2(u32 h) {
    float lo, hi;
    asm("{\n\t.reg .f16 l, u;\n\t"
        "mov.b32 {l, u}, %2;\n\t"
        "cvt.f32.f16 %0, l;\n\t"
        "cvt.f32.f16 %1, u;\n\t}"
        : "=f"(lo), "=f"(hi) : "r"(h));
    return make_float2(lo, hi);
}
__device__ __forceinline__ ull pack2(float a, float b) {
    ull r; asm("mov.b64 %0, {%1, %2};" : "=l"(r) : "f"(a), "f"(b)); return r;
}
__device__ __forceinline__ ull fma2(ull a, ull b, ull c) {
    ull d; asm("fma.rn.f32x2 %0, %1, %2, %3;" : "=l"(d) : "l"(a), "l"(b), "l"(c)); return d;
}
__device__ __forceinline__ float2 unpack2(ull a) {
    float lo, hi; asm("mov.b64 {%0, %1}, %2;" : "=f"(lo), "=f"(hi) : "l"(a));
    return make_float2(lo, hi);
}

// ---------------------------------------------------------------------------
// Phase 1: scores[b,c,p] = sum_d tanh(img[b,d,p]*word[c,d]) * w[d]
// f16x2 fast path: x = im*wd via HMUL2, packed tanh.approx.f16x2 (2 tanh per
// MUFU inst), unpack to f32, FFMA against f32 fc_a_w. Word rows converted to
// f16x2 at chunk-staging time (halves inner LDS traffic).
// Also writes imgT[b,p,d] (f32, coalesced) for phase 3.
// grid (25, 16), block 256, 3 blocks/SM (single wave: 400 <= 444).
// Thread owns 32 d's as 16 f16x2 pairs; d-group base = 8*(lane+32k).
// ---------------------------------------------------------------------------
__global__ __launch_bounds__(256, 3) void scores_kernel(
    const float* __restrict__ img,      // [B][D][P]
    const float* __restrict__ word,     // [C][D]
    const float* __restrict__ faw)      // [D]
{
    extern __shared__ float sm[];               // img staging, then f16x2 word chunks

    const int b  = blockIdx.y;
    const int p0 = blockIdx.x * PT;
    const int tid = threadIdx.x;

    // --- Stage img tile: [PT pixels][D] -> smem (tail pixels clamp) ---
    const float* imgb = img + (size_t)b * DD * PP;
    for (int i = tid; i < PT * DD; i += 256) {
        int p = i & (PT - 1), d = i >> 3;
        int gp = p0 + p; if (gp >= PP) gp = PP - 1;
        sm[p * SSTRIDE + d] = imgb[d * PP + gp];
    }
    __syncthreads();

    const int lane = tid & 31, w = tid >> 5;
    const int p = p0 + w;
    const bool valid = (p < PP);

    // Register-cache img slice as f16x2 pairs + fc_a_w slice in f32,
    // and emit transposed img (f32, coalesced float4 stores) for phase 3.
    u32 im2[16];
    float4 wv[8];
    const float4* faw4 = (const float4*)faw;
    {
        int pr = valid ? p : (PP - 1);
        float4* outT = (float4*)(g_imgT + ((size_t)b * PP + pr) * DD);
        const float4* row = (const float4*)&sm[w * SSTRIDE];
        #pragma unroll
        for (int k = 0; k < 4; k++) {
            int base = 2 * (lane + 32 * k);      // float4 index (d = 4*base)
            float4 v0 = row[base], v1 = row[base + 1];
            im2[4*k+0] = pack_f16x2(v0.y, v0.x);
            im2[4*k+1] = pack_f16x2(v0.w, v0.z);
            im2[4*k+2] = pack_f16x2(v1.y, v1.x);
            im2[4*k+3] = pack_f16x2(v1.w, v1.z);
            wv[2*k]   = faw4[base];
            wv[2*k+1] = faw4[base + 1];
            if (valid) { outT[base] = v0; outT[base + 1] = v1; }
        }
    }
    __syncthreads();   // img staging dead; smem now belongs to f16x2 word chunks

    float* scb = g_scores + (size_t)b * CC * PP + p;
    const float4* word4 = (const float4*)word;
    u32* smw = (u32*)sm;

    #pragma unroll 1
    for (int c0 = 0; c0 < CC; c0 += CHUNK) {
        // Cooperative load+convert of CHUNK word rows to f16x2 (32KB)
        const float4* src = word4 + (size_t)c0 * (DD / 4);
        #pragma unroll
        for (int i = 0; i < CHUNK * DD / 4 / 256; i++) {     // 16 iters
            float4 v = src[tid + 256 * i];
            uint2 h = make_uint2(pack_f16x2(v.y, v.x), pack_f16x2(v.w, v.z));
            ((uint2*)smw)[tid + 256 * i] = h;
        }
        __syncthreads();

        #pragma unroll 1
        for (int cc = 0; cc < CHUNK; cc++) {
            const uint4* ws = (const uint4*)(smw + cc * (DD / 2));
            float a0 = 0.f, a1 = 0.f, a2 = 0.f, a3 = 0.f;
            #pragma unroll
            for (int k = 0; k < 4; k++) {
                uint4 wd = ws[lane + 32 * k];    // conflict-free LDS.128, 8 d's
                float2 f;
                f = unpack_f16x2(htanh2(hmul2(im2[4*k+0], wd.x)));
                a0 = fmaf(f.x, wv[2*k].x, a0);   a1 = fmaf(f.y, wv[2*k].y, a1);
                f = unpack_f16x2(htanh2(hmul2(im2[4*k+1], wd.y)));
                a2 = fmaf(f.x, wv[2*k].z, a2);   a3 = fmaf(f.y, wv[2*k].w, a3);
                f = unpack_f16x2(htanh2(hmul2(im2[4*k+2], wd.z)));
                a0 = fmaf(f.x, wv[2*k+1].x, a0); a1 = fmaf(f.y, wv[2*k+1].y, a1);
                f = unpack_f16x2(htanh2(hmul2(im2[4*k+3], wd.w)));
                a2 = fmaf(f.x, wv[2*k+1].z, a2); a3 = fmaf(f.y, wv[2*k+1].w, a3);
            }
            float acc = (a0 + a1) + (a2 + a3);
            #pragma unroll
            for (int o = 16; o; o >>= 1)
                acc += __shfl_xor_sync(0xFFFFFFFFu, acc, o);
            if (lane == 0 && valid)
                scb[(c0 + cc) * PP] = acc;
            // fc_a_b is a uniform shift over spatial scores -> softmax-invariant
        }
        __syncthreads();   // chunk consumed; safe to overwrite
    }
}

// ---------------------------------------------------------------------------
// Phase 2: coef[b,p,c] = softmax over p of scores[b,c,p]. One warp per (b,c).
// ---------------------------------------------------------------------------
__global__ __launch_bounds__(256) void softmax_kernel()
{
    const int gw   = blockIdx.x * 8 + (threadIdx.x >> 5);   // 0..1279
    const int lane = threadIdx.x & 31;
    const int b = gw / CC, c = gw % CC;

    const float* sc = g_scores + ((size_t)b * CC + c) * PP;
    float v[7];
    float mx = -1e30f;
    #pragma unroll
    for (int k = 0; k < 7; k++) {
        int p = lane + 32 * k;
        v[k] = (p < PP) ? sc[p] : -1e30f;
        mx = fmaxf(mx, v[k]);
    }
    #pragma unroll
    for (int o = 16; o; o >>= 1)
        mx = fmaxf(mx, __shfl_xor_sync(0xFFFFFFFFu, mx, o));

    float sum = 0.f;
    #pragma unroll
    for (int k = 0; k < 7; k++) {
        v[k] = __expf(v[k] - mx);      // invalid p -> exp(-inf) = 0
        sum += v[k];
    }
    #pragma unroll
    for (int o = 16; o; o >>= 1)
        sum += __shfl_xor_sync(0xFFFFFFFFu, sum, o);

    float inv = 1.0f / sum;
    #pragma unroll
    for (int k = 0; k < 7; k++) {
        int p = lane + 32 * k;
        if (p < PP)
            g_coef[((size_t)b * PP + p) * CC + c] = v[k] * inv;
    }
}

// ---------------------------------------------------------------------------
// Phase 3: out[b,c,d] = sum_p coef[b,p,c] * imgT[b,p,d]
// grid (8 d-tiles of 128, 16 b), block 256 (163KB dyn smem, 1 block/SM).
// Thread tile: 10 c x 4 d, packed fma.rn.f32x2 (pairs over c).
// ---------------------------------------------------------------------------
__global__ __launch_bounds__(256) void out_kernel(float* __restrict__ out)
{
    extern __shared__ float sm[];
    float* img_s  = sm;                 // [196][128]
    float* coef_s = sm + PP * 128;      // [196][80]

    const int b  = blockIdx.y;
    const int d0 = blockIdx.x * 128;
    const int tid = threadIdx.x;

    const float* imgT = g_imgT + (size_t)b * PP * DD;
    for (int i = tid; i < PP * 32; i += 256) {   // 196 * 128/4 float4s
        int pp = i >> 5, j = i & 31;
        ((float4*)img_s)[pp * 32 + j] = *(const float4*)(imgT + (size_t)pp * DD + d0 + 4 * j);
    }
    const float4* coefb = (const float4*)(g_coef + (size_t)b * PP * CC);
    for (int i = tid; i < PP * 20; i += 256)     // 196 * 80/4 float4s
        ((float4*)coef_s)[i] = coefb[i];
    __syncthreads();

    const int dg = tid & 31;            // lanes over d-quads (conflict-free LDS.128)
    const int cg = tid >> 5;            // warp = c-group (broadcast coef LDS.64)

    ull acc[5][4];
    #pragma unroll
    for (int j = 0; j < 5; j++)
        #pragma unroll
        for (int dd = 0; dd < 4; dd++) acc[j][dd] = 0ull;

    #pragma unroll 2
    for (int p = 0; p < PP; p++) {
        float4 iv = ((const float4*)img_s)[p * 32 + dg];
        ull ix = pack2(iv.x, iv.x);
        ull iy = pack2(iv.y, iv.y);
        ull iz = pack2(iv.z, iv.z);
        ull iw = pack2(iv.w, iv.w);
        const ull* cpr = (const ull*)(coef_s + p * CC + cg * 10);
        #pragma unroll
        for (int j = 0; j < 5; j++) {
            ull cc = cpr[j];            // (coef[c], coef[c+1])
            acc[j][0] = fma2(cc, ix, acc[j][0]);
            acc[j][1] = fma2(cc, iy, acc[j][1]);
            acc[j][2] = fma2(cc, iz, acc[j][2]);
            acc[j][3] = fma2(cc, iw, acc[j][3]);
        }
    }

    #pragma unroll
    for (int j = 0; j < 5; j++) {
        int c = cg * 10 + 2 * j;
        #pragma unroll
        for (int dd = 0; dd < 4; dd++) {
            float2 v = unpack2(acc[j][dd]);
            int d = d0 + 4 * dg + dd;
            out[((size_t)(b * CC + c))     * DD + d] = v.x;
            out[((size_t)(b * CC + c + 1)) * DD + d] = v.y;
        }
    }
}

// ---------------------------------------------------------------------------
extern "C" void kernel_launch(void* const* d_in, const int* in_sizes, int n_in,
                              void* d_out, int out_size)
{
    // inputs: [0]=batch_size (unused), [1]=img [16,1024,14,14],
    //         [2]=word [80,1024], [3]=fc_a_w [1024], [4]=fc_a_b (softmax-invariant)
    const float* img  = (const float*)d_in[1];
    const float* word = (const float*)d_in[2];
    const float* faw  = (const float*)d_in[3];
    float* out = (float*)d_out;

    const int smem1 = PT * SSTRIDE * (int)sizeof(float);          // 33,024 B (>= 32KB chunk)
    const int smem3 = (PP * 128 + PP * CC) * (int)sizeof(float);  // 163,072 B
    cudaFuncSetAttribute(scores_kernel, cudaFuncAttributeMaxDynamicSharedMemorySize, smem1);
    cudaFuncSetAttribute(out_kernel, cudaFuncAttributeMaxDynamicSharedMemorySize, smem3);

    scores_kernel<<<dim3(25, BB), 256, smem1>>>(img, word, faw);
    softmax_kernel<<<160, 256>>>();
    out_kernel<<<dim3(8, BB), 256, smem3>>>(out);
}